// round 9
// baseline (speedup 1.0000x reference)
#include <cuda_runtime.h>
#include <cuda_bf16.h>
#include <math.h>

// ---------------- constants ----------------
#define HDIM 128
#define GDIM 51
#define TPT  8192
#define RMAX 1.7330f
#define TAB_H   (RMAX / (float)(TPT - 1))
#define TAB_INVH ((float)(TPT - 1) / RMAX)
#define MAXN 100000

// ---------------- scratch ----------------
__device__ __align__(16) float g_x1 [MAXN * HDIM];
__device__ __align__(16) float g_agg[MAXN * HDIM];
__device__ __align__(16) float g_tab[TPT  * HDIM];   // 4MB, L2-resident
__device__ int g_is64;

__device__ __forceinline__ float sspf(float x) {
    float sp = fmaxf(x, 0.0f) + log1pf(__expf(-fabsf(x)));
    return sp - 0.6931471805599453f;
}

// ---------------- dtype sniff ----------------
__global__ void detect_kernel(const unsigned* __restrict__ ei, int E) {
    __shared__ unsigned red[256];
    unsigned acc = 0;
    int total = 2 * E;
    for (int i = threadIdx.x; i < 2048; i += 256) {
        long long w = 2LL * i + 1;
        if (w < total) acc |= ei[w];
    }
    red[threadIdx.x] = acc;
    __syncthreads();
    for (int s = 128; s > 0; s >>= 1) {
        if (threadIdx.x < s) red[threadIdx.x] |= red[threadIdx.x + s];
        __syncthreads();
    }
    if (threadIdx.x == 0) g_is64 = (red[0] == 0u) ? 1 : 0;
}

// ---------------- zero ----------------
__global__ void zero_kernel(int n4) {
    int i = blockIdx.x * blockDim.x + threadIdx.x;
    if (i < n4) ((float4*)g_agg)[i] = make_float4(0.f, 0.f, 0.f, 0.f);
}

// ---------------- filter table (fp32, fine grid for nearest lookup) ----------------
__global__ void table_kernel(const float* __restrict__ mlp0_w, const float* __restrict__ mlp0_b,
                             const float* __restrict__ mlp2_w, const float* __restrict__ mlp2_b) {
    __shared__ float ea[GDIM];
    __shared__ float hid[HDIM];
    const int f = threadIdx.x;
    const int p = blockIdx.x;
    const float ew = (float)p * TAB_H;

    if (f < GDIM) {
        float off = (float)f * 0.2f;
        float d = ew - off;
        ea[f] = expf(-12.5f * d * d);
    }
    __syncthreads();

    float a = mlp0_b[f];
    #pragma unroll
    for (int g = 0; g < GDIM; ++g)
        a = fmaf(ea[g], mlp0_w[f * GDIM + g], a);
    hid[f] = sspf(a);
    __syncthreads();

    float b = mlp2_b[f];
    #pragma unroll 8
    for (int k = 0; k < HDIM; ++k)
        b = fmaf(hid[k], mlp2_w[f * HDIM + k], b);

    float C = 0.5f * (cosf(ew * 0.31415926535897931f) + 1.0f);
    g_tab[p * HDIM + f] = b * C;
}

// ---------------- edge kernel: nearest-neighbor table, 1.5KB L2/edge ----------------
__global__ __launch_bounds__(256) void edge_kernel(const void* __restrict__ ei_raw,
                                                   const float* __restrict__ pos, int E) {
    const int lane = threadIdx.x & 31;
    const int warp = threadIdx.x >> 5;
    const int base = (blockIdx.x * 8 + warp) * 32;
    if (base >= E) return;

    const int is64 = g_is64;

    int r = 0, c = 0, i0 = 0;
    const int e = base + lane;
    if (e < E) {
        if (is64) {
            const long long* ei = (const long long*)ei_raw;
            r = (int)ei[e];
            c = (int)ei[(size_t)E + e];
        } else {
            const int* ei = (const int*)ei_raw;
            r = ei[e];
            c = ei[(size_t)E + e];
        }
        float ax = __ldg(pos + 3 * r), ay = __ldg(pos + 3 * r + 1), az = __ldg(pos + 3 * r + 2);
        float bx = __ldg(pos + 3 * c), by = __ldg(pos + 3 * c + 1), bz = __ldg(pos + 3 * c + 2);
        float dx = ax - bx, dy = ay - by, dz = az - bz;
        float ew = sqrtf(fmaf(dx, dx, fmaf(dy, dy, fmaf(dz, dz, 1e-12f))));
        i0 = (int)(ew * TAB_INVH + 0.5f);     // nearest
        if (i0 > TPT - 1) i0 = TPT - 1;
    }

    int nv = E - base; if (nv > 32) nv = 32;
    for (int j = 0; j < nv; ++j) {
        int rr = __shfl_sync(0xffffffffu, r,  j);
        int cc = __shfl_sync(0xffffffffu, c,  j);
        int ii = __shfl_sync(0xffffffffu, i0, j);

        float4 xv = __ldg((const float4*)g_x1  + (size_t)rr * 32 + lane);
        float4 wv = __ldg((const float4*)g_tab + (size_t)ii * 32 + lane);

        float m0 = xv.x * wv.x, m1 = xv.y * wv.y, m2 = xv.z * wv.z, m3 = xv.w * wv.w;

        float* p = g_agg + (size_t)cc * HDIM + lane * 4;
        asm volatile("red.global.add.v4.f32 [%0], {%1, %2, %3, %4};"
                     :: "l"(p), "f"(m0), "f"(m1), "f"(m2), "f"(m3) : "memory");
    }
}

// ---------------- fused multi-stage GEMM (R7 exact) ----------------
struct Stages {
    const float* W[4];
    const float* bias[4];
    const float* res[4];
    int flags[4];          // bit0 = ssp
    int count;
};

#define FUSED_SMEM ((128 * 128 + 256 * 128) * 4)   // 64KB ws + 128KB xs = 192KB

__global__ __launch_bounds__(512, 1) void fused_kernel(
    const float* __restrict__ X, float* __restrict__ Y, Stages st, int n)
{
    extern __shared__ float sm[];
    float* ws = sm;                 // permuted [k][128]
    float* xs = sm + 128 * 128;     // [256][128]

    const int tid  = threadIdx.x;
    const int row0 = blockIdx.x << 8;            // 256 rows per tile
    const int tx = tid & 15, ty = tid >> 4;      // ty 0..31

    // ---- load X tile (clamped rows) ----
    {
        const float4* X4 = (const float4*)X;
        #pragma unroll
        for (int it = 0; it < 16; ++it) {
            int idx = tid + it * 512;            // 0..8191
            int r = idx >> 5, kq = idx & 31;
            int gr = row0 + r; if (gr > n - 1) gr = n - 1;
            *(float4*)(xs + r * 128 + kq * 4) = __ldg(X4 + (size_t)gr * 32 + kq);
        }
    }

    for (int s = 0; s < st.count; ++s) {
        const float* W = st.W[s];
        #pragma unroll
        for (int it = 0; it < 8; ++it) {
            int idx = tid + it * 512;
            int o = idx & 127, kq = idx >> 7;
            float4 v = __ldg((const float4*)W + o * 32 + kq);
            int t = o >> 3, half = (o >> 2) & 1, j = o & 3;
            int base = half * 64 + t * 4 + j;
            ws[(kq * 4 + 0) * 128 + base] = v.x;
            ws[(kq * 4 + 1) * 128 + base] = v.y;
            ws[(kq * 4 + 2) * 128 + base] = v.z;
            ws[(kq * 4 + 3) * 128 + base] = v.w;
        }
        __syncthreads();

        unsigned long long acc[8][4];
        #pragma unroll
        for (int i = 0; i < 8; ++i)
            #pragma unroll
            for (int m = 0; m < 4; ++m) acc[i][m] = 0ull;

        #pragma unroll 8
        for (int kb = 0; kb < 32; ++kb) {
            float4 xv[8];
            #pragma unroll
            for (int i = 0; i < 8; ++i)
                xv[i] = *(const float4*)(xs + (ty * 8 + i) * 128 + kb * 4);

            #pragma unroll
            for (int dk = 0; dk < 4; ++dk) {
                const int k = kb * 4 + dk;
                ulonglong2 wa = *(const ulonglong2*)(ws + (k << 7) + (tx << 2));
                ulonglong2 wb = *(const ulonglong2*)(ws + (k << 7) + 64 + (tx << 2));
                #pragma unroll
                for (int i = 0; i < 8; ++i) {
                    float xsv = (dk == 0) ? xv[i].x : (dk == 1) ? xv[i].y
                              : (dk == 2) ? xv[i].z : xv[i].w;
                    unsigned xu = __float_as_uint(xsv);
                    unsigned long long x2;
                    asm("mov.b64 %0, {%1, %1};" : "=l"(x2) : "r"(xu));
                    asm("fma.rn.f32x2 %0, %1, %2, %0;" : "+l"(acc[i][0]) : "l"(x2), "l"(wa.x));
                    asm("fma.rn.f32x2 %0, %1, %2, %0;" : "+l"(acc[i][1]) : "l"(x2), "l"(wa.y));
                    asm("fma.rn.f32x2 %0, %1, %2, %0;" : "+l"(acc[i][2]) : "l"(x2), "l"(wb.x));
                    asm("fma.rn.f32x2 %0, %1, %2, %0;" : "+l"(acc[i][3]) : "l"(x2), "l"(wb.y));
                }
            }
        }
        __syncthreads();

        const float* bias = st.bias[s];
        const float* res  = st.res[s];
        const int flags   = st.flags[s];
        const int col = tx << 3;
        float4 b0 = make_float4(0.f, 0.f, 0.f, 0.f), b1 = b0;
        if (bias) {
            b0 = __ldg((const float4*)bias + tx * 2);
            b1 = __ldg((const float4*)bias + tx * 2 + 1);
        }
        const bool last = (s == st.count - 1);
        #pragma unroll
        for (int i = 0; i < 8; ++i) {
            int lr = ty * 8 + i;
            int r = row0 + lr;
            float2 p0 = *(float2*)&acc[i][0];
            float2 p1 = *(float2*)&acc[i][1];
            float2 p2 = *(float2*)&acc[i][2];
            float2 p3 = *(float2*)&acc[i][3];
            float4 v0 = make_float4(p0.x + b0.x, p0.y + b0.y, p1.x + b0.z, p1.y + b0.w);
            float4 v1 = make_float4(p2.x + b1.x, p2.y + b1.y, p3.x + b1.z, p3.y + b1.w);
            if (flags & 1) {
                v0.x = sspf(v0.x); v0.y = sspf(v0.y); v0.z = sspf(v0.z); v0.w = sspf(v0.w);
                v1.x = sspf(v1.x); v1.y = sspf(v1.y); v1.z = sspf(v1.z); v1.w = sspf(v1.w);
            }
            if (res) {
                int gr = r > n - 1 ? n - 1 : r;
                float4 r0 = __ldg((const float4*)(res + (size_t)gr * HDIM + col));
                float4 r1 = __ldg((const float4*)(res + (size_t)gr * HDIM + col + 4));
                v0.x += r0.x; v0.y += r0.y; v0.z += r0.z; v0.w += r0.w;
                v1.x += r1.x; v1.y += r1.y; v1.z += r1.z; v1.w += r1.w;
            }
            if (last) {
                if (r < n) {
                    *(float4*)(Y + (size_t)r * HDIM + col)     = v0;
                    *(float4*)(Y + (size_t)r * HDIM + col + 4) = v1;
                }
            } else {
                *(float4*)(xs + lr * 128 + col)     = v0;
                *(float4*)(xs + lr * 128 + col + 4) = v1;
            }
        }
        __syncthreads();
    }
}

// ---------------- launch ----------------
extern "C" void kernel_launch(void* const* d_in, const int* in_sizes, int n_in,
                              void* d_out, int out_size) {
    const float* z      = (const float*)d_in[0];
    const float* pos    = (const float*)d_in[1];
    const void*  ei     = d_in[2];
    const float* lin1_w = (const float*)d_in[3];
    const float* lin2_w = (const float*)d_in[4];
    const float* lin2_b = (const float*)d_in[5];
    const float* mlp0_w = (const float*)d_in[6];
    const float* mlp0_b = (const float*)d_in[7];
    const float* mlp2_w = (const float*)d_in[8];
    const float* mlp2_b = (const float*)d_in[9];
    const float* blk_w  = (const float*)d_in[10];
    const float* blk_b  = (const float*)d_in[11];
    const float* out1_w = (const float*)d_in[12];
    const float* out1_b = (const float*)d_in[13];
    const float* out2_w = (const float*)d_in[14];
    const float* out2_b = (const float*)d_in[15];
    float* out = (float*)d_out;

    const int n = in_sizes[0] / HDIM;
    const int E = in_sizes[2] / 2;

    float *x1p, *aggp;
    cudaGetSymbolAddress((void**)&x1p,  g_x1);
    cudaGetSymbolAddress((void**)&aggp, g_agg);

    cudaFuncSetAttribute(fused_kernel, cudaFuncAttributeMaxDynamicSharedMemorySize, FUSED_SMEM);

    const int fblocks = (n + 255) / 256;
    const int n4 = n * 32;

    detect_kernel<<<1, 256>>>((const unsigned*)ei, E);
    zero_kernel<<<(n4 + 255) / 256, 256>>>(n4);
    table_kernel<<<TPT, HDIM>>>(mlp0_w, mlp0_b, mlp2_w, mlp2_b);

    // x1 = z @ lin1^T
    Stages s1 = {};
    s1.W[0] = lin1_w; s1.bias[0] = nullptr; s1.res[0] = nullptr; s1.flags[0] = 0;
    s1.count = 1;
    fused_kernel<<<fblocks, 512, FUSED_SMEM>>>(z, x1p, s1, n);

    // scatter: agg[col] += x1[row] * tab[nearest(ew)]
    edge_kernel<<<(E + 255) / 256, 256>>>(ei, pos, E);

    // fused tail
    Stages s2 = {};
    s2.W[0] = lin2_w; s2.bias[0] = lin2_b; s2.res[0] = nullptr; s2.flags[0] = 1;
    s2.W[1] = blk_w;  s2.bias[1] = blk_b;  s2.res[1] = z;       s2.flags[1] = 0;
    s2.W[2] = out1_w; s2.bias[2] = out1_b; s2.res[2] = nullptr; s2.flags[2] = 1;
    s2.W[3] = out2_w; s2.bias[3] = out2_b; s2.res[3] = nullptr; s2.flags[3] = 0;
    s2.count = 4;
    fused_kernel<<<fblocks, 512, FUSED_SMEM>>>(aggp, out, s2, n);
}

// round 15
// speedup vs baseline: 1.2608x; 1.2608x over previous
#include <cuda_runtime.h>
#include <cuda_bf16.h>
#include <cuda_fp16.h>
#include <math.h>

// ---------------- constants ----------------
#define HDIM 128
#define GDIM 51
#define TPT  2048
#define RMAX 1.7330f
#define TAB_H   (RMAX / (float)(TPT - 1))
#define TAB_INVH ((float)(TPT - 1) / RMAX)
#define MAXN 100000

// ---------------- scratch ----------------
__device__ __align__(16)  float  g_x1  [MAXN * HDIM];
__device__ __align__(256) __half g_aggh[MAXN * HDIM];   // fp16 accumulator
__device__ __align__(16)  float  g_tab [TPT  * HDIM];   // 1MB, L2-hot
__device__ int g_is64;

__device__ __forceinline__ float sspf(float x) {
    float sp = fmaxf(x, 0.0f) + log1pf(__expf(-fabsf(x)));
    return sp - 0.6931471805599453f;
}

// ---------------- dtype sniff ----------------
__global__ void detect_kernel(const unsigned* __restrict__ ei, int E) {
    __shared__ unsigned red[256];
    unsigned acc = 0;
    int total = 2 * E;
    for (int i = threadIdx.x; i < 2048; i += 256) {
        long long w = 2LL * i + 1;
        if (w < total) acc |= ei[w];
    }
    red[threadIdx.x] = acc;
    __syncthreads();
    for (int s = 128; s > 0; s >>= 1) {
        if (threadIdx.x < s) red[threadIdx.x] |= red[threadIdx.x + s];
        __syncthreads();
    }
    if (threadIdx.x == 0) g_is64 = (red[0] == 0u) ? 1 : 0;
}

// ---------------- zero (fp16 agg): n*16 uint4 per n rows ----------------
__global__ void zero_kernel(int n16) {
    int i = blockIdx.x * blockDim.x + threadIdx.x;
    if (i < n16) ((uint4*)g_aggh)[i] = make_uint4(0u, 0u, 0u, 0u);
}

// ---------------- filter table (fp32, TPT=2048, lerp) ----------------
__global__ void table_kernel(const float* __restrict__ mlp0_w, const float* __restrict__ mlp0_b,
                             const float* __restrict__ mlp2_w, const float* __restrict__ mlp2_b) {
    __shared__ float ea[GDIM];
    __shared__ float hid[HDIM];
    const int f = threadIdx.x;
    const int p = blockIdx.x;
    const float ew = (float)p * TAB_H;

    if (f < GDIM) {
        float off = (float)f * 0.2f;
        float d = ew - off;
        ea[f] = expf(-12.5f * d * d);
    }
    __syncthreads();

    float a = mlp0_b[f];
    #pragma unroll
    for (int g = 0; g < GDIM; ++g)
        a = fmaf(ea[g], mlp0_w[f * GDIM + g], a);
    hid[f] = sspf(a);
    __syncthreads();

    float b = mlp2_b[f];
    #pragma unroll 8
    for (int k = 0; k < HDIM; ++k)
        b = fmaf(hid[k], mlp2_w[f * HDIM + k], b);

    float C = 0.5f * (cosf(ew * 0.31415926535897931f) + 1.0f);
    g_tab[p * HDIM + f] = b * C;
}

// ---------------- edge kernel: 8 lanes/edge, 2x v4.f16x2 RED ----------------
__global__ __launch_bounds__(256) void edge_kernel(const void* __restrict__ ei_raw,
                                                   const float* __restrict__ pos, int E) {
    const int lane = threadIdx.x & 31;
    const int warp = threadIdx.x >> 5;
    const int base = (blockIdx.x * 8 + warp) * 32;
    if (base >= E) return;

    const int is64 = g_is64;

    int r = 0, c = 0, i0 = 0; float fr = 0.f;
    const int e = base + lane;
    if (e < E) {
        if (is64) {
            const long long* ei = (const long long*)ei_raw;
            r = (int)ei[e];
            c = (int)ei[(size_t)E + e];
        } else {
            const int* ei = (const int*)ei_raw;
            r = ei[e];
            c = ei[(size_t)E + e];
        }
        float ax = __ldg(pos + 3 * r), ay = __ldg(pos + 3 * r + 1), az = __ldg(pos + 3 * r + 2);
        float bx = __ldg(pos + 3 * c), by = __ldg(pos + 3 * c + 1), bz = __ldg(pos + 3 * c + 2);
        float dx = ax - bx, dy = ay - by, dz = az - bz;
        float ew = sqrtf(fmaf(dx, dx, fmaf(dy, dy, fmaf(dz, dz, 1e-12f))));
        float t = ew * TAB_INVH;
        i0 = (int)t;
        if (i0 > TPT - 2) i0 = TPT - 2;
        fr = t - (float)i0;
    }

    const int q    = lane >> 3;   // edge-within-group 0..3
    const int part = lane & 7;    // 16-col slice 0..7

    int nv = E - base; if (nv > 32) nv = 32;
    for (int j0 = 0; j0 < nv; j0 += 4) {
        int src = j0 + q;
        int   rr = __shfl_sync(0xffffffffu, r,  src & 31);
        int   cc = __shfl_sync(0xffffffffu, c,  src & 31);
        int   ii = __shfl_sync(0xffffffffu, i0, src & 31);
        float ff = __shfl_sync(0xffffffffu, fr, src & 31);

        if (src < nv) {
            const float4* xp  = (const float4*)(g_x1  + (size_t)rr * HDIM + part * 16);
            const float4* w0p = (const float4*)(g_tab + (size_t)ii * HDIM + part * 16);
            const float4* w1p = (const float4*)(g_tab + (size_t)(ii + 1) * HDIM + part * 16);

            unsigned h[8];
            #pragma unroll
            for (int t = 0; t < 4; ++t) {
                float4 xv = __ldg(xp  + t);
                float4 a0 = __ldg(w0p + t);
                float4 a1 = __ldg(w1p + t);
                float wx = fmaf(ff, a1.x - a0.x, a0.x);
                float wy = fmaf(ff, a1.y - a0.y, a0.y);
                float wz = fmaf(ff, a1.z - a0.z, a0.z);
                float ww = fmaf(ff, a1.w - a0.w, a0.w);
                __half2 h0 = __floats2half2_rn(xv.x * wx, xv.y * wy);
                __half2 h1 = __floats2half2_rn(xv.z * wz, xv.w * ww);
                h[t * 2]     = *(unsigned*)&h0;
                h[t * 2 + 1] = *(unsigned*)&h1;
            }

            __half* p = g_aggh + (size_t)cc * HDIM + part * 16;
            asm volatile("red.global.add.noftz.v4.f16x2 [%0], {%1,%2,%3,%4};"
                         :: "l"(p), "r"(h[0]), "r"(h[1]), "r"(h[2]), "r"(h[3]) : "memory");
            asm volatile("red.global.add.noftz.v4.f16x2 [%0], {%1,%2,%3,%4};"
                         :: "l"(p + 8), "r"(h[4]), "r"(h[5]), "r"(h[6]), "r"(h[7]) : "memory");
        }
    }
}

// ---------------- fused multi-stage GEMM (R7 core, + fp16-input mode) ----------------
struct Stages {
    const float* W[4];
    const float* bias[4];
    const float* res[4];
    int flags[4];          // bit0 = ssp
    int count;
};

#define FUSED_SMEM ((128 * 128 + 256 * 128) * 4)   // 64KB ws + 128KB xs = 192KB

__global__ __launch_bounds__(512, 1) void fused_kernel(
    const float* __restrict__ X, float* __restrict__ Y, Stages st, int n, int in_half)
{
    extern __shared__ float sm[];
    float* ws = sm;                 // permuted [k][128]
    float* xs = sm + 128 * 128;     // [256][128]

    const int tid  = threadIdx.x;
    const int row0 = blockIdx.x << 8;
    const int tx = tid & 15, ty = tid >> 4;

    // ---- load X tile ----
    if (in_half) {
        const uint2* X2 = (const uint2*)X;
        #pragma unroll
        for (int it = 0; it < 16; ++it) {
            int idx = tid + it * 512;
            int r = idx >> 5, kq = idx & 31;
            int gr = row0 + r; if (gr > n - 1) gr = n - 1;
            uint2 v = __ldg(X2 + (size_t)gr * 32 + kq);
            float2 a = __half22float2(*(__half2*)&v.x);
            float2 b = __half22float2(*(__half2*)&v.y);
            *(float4*)(xs + r * 128 + kq * 4) = make_float4(a.x, a.y, b.x, b.y);
        }
    } else {
        const float4* X4 = (const float4*)X;
        #pragma unroll
        for (int it = 0; it < 16; ++it) {
            int idx = tid + it * 512;
            int r = idx >> 5, kq = idx & 31;
            int gr = row0 + r; if (gr > n - 1) gr = n - 1;
            *(float4*)(xs + r * 128 + kq * 4) = __ldg(X4 + (size_t)gr * 32 + kq);
        }
    }

    for (int s = 0; s < st.count; ++s) {
        const float* W = st.W[s];
        #pragma unroll
        for (int it = 0; it < 8; ++it) {
            int idx = tid + it * 512;
            int o = idx & 127, kq = idx >> 7;
            float4 v = __ldg((const float4*)W + o * 32 + kq);
            int t = o >> 3, half = (o >> 2) & 1, j = o & 3;
            int base = half * 64 + t * 4 + j;
            ws[(kq * 4 + 0) * 128 + base] = v.x;
            ws[(kq * 4 + 1) * 128 + base] = v.y;
            ws[(kq * 4 + 2) * 128 + base] = v.z;
            ws[(kq * 4 + 3) * 128 + base] = v.w;
        }
        __syncthreads();

        unsigned long long acc[8][4];
        #pragma unroll
        for (int i = 0; i < 8; ++i)
            #pragma unroll
            for (int m = 0; m < 4; ++m) acc[i][m] = 0ull;

        #pragma unroll 8
        for (int kb = 0; kb < 32; ++kb) {
            float4 xv[8];
            #pragma unroll
            for (int i = 0; i < 8; ++i)
                xv[i] = *(const float4*)(xs + (ty * 8 + i) * 128 + kb * 4);

            #pragma unroll
            for (int dk = 0; dk < 4; ++dk) {
                const int k = kb * 4 + dk;
                ulonglong2 wa = *(const ulonglong2*)(ws + (k << 7) + (tx << 2));
                ulonglong2 wb = *(const ulonglong2*)(ws + (k << 7) + 64 + (tx << 2));
                #pragma unroll
                for (int i = 0; i < 8; ++i) {
                    float xsv = (dk == 0) ? xv[i].x : (dk == 1) ? xv[i].y
                              : (dk == 2) ? xv[i].z : xv[i].w;
                    unsigned xu = __float_as_uint(xsv);
                    unsigned long long x2;
                    asm("mov.b64 %0, {%1, %1};" : "=l"(x2) : "r"(xu));
                    asm("fma.rn.f32x2 %0, %1, %2, %0;" : "+l"(acc[i][0]) : "l"(x2), "l"(wa.x));
                    asm("fma.rn.f32x2 %0, %1, %2, %0;" : "+l"(acc[i][1]) : "l"(x2), "l"(wa.y));
                    asm("fma.rn.f32x2 %0, %1, %2, %0;" : "+l"(acc[i][2]) : "l"(x2), "l"(wb.x));
                    asm("fma.rn.f32x2 %0, %1, %2, %0;" : "+l"(acc[i][3]) : "l"(x2), "l"(wb.y));
                }
            }
        }
        __syncthreads();

        const float* bias = st.bias[s];
        const float* res  = st.res[s];
        const int flags   = st.flags[s];
        const int col = tx << 3;
        float4 b0 = make_float4(0.f, 0.f, 0.f, 0.f), b1 = b0;
        if (bias) {
            b0 = __ldg((const float4*)bias + tx * 2);
            b1 = __ldg((const float4*)bias + tx * 2 + 1);
        }
        const bool last = (s == st.count - 1);
        #pragma unroll
        for (int i = 0; i < 8; ++i) {
            int lr = ty * 8 + i;
            int r = row0 + lr;
            float2 p0 = *(float2*)&acc[i][0];
            float2 p1 = *(float2*)&acc[i][1];
            float2 p2 = *(float2*)&acc[i][2];
            float2 p3 = *(float2*)&acc[i][3];
            float4 v0 = make_float4(p0.x + b0.x, p0.y + b0.y, p1.x + b0.z, p1.y + b0.w);
            float4 v1 = make_float4(p2.x + b1.x, p2.y + b1.y, p3.x + b1.z, p3.y + b1.w);
            if (flags & 1) {
                v0.x = sspf(v0.x); v0.y = sspf(v0.y); v0.z = sspf(v0.z); v0.w = sspf(v0.w);
                v1.x = sspf(v1.x); v1.y = sspf(v1.y); v1.z = sspf(v1.z); v1.w = sspf(v1.w);
            }
            if (res) {
                int gr = r > n - 1 ? n - 1 : r;
                float4 r0 = __ldg((const float4*)(res + (size_t)gr * HDIM + col));
                float4 r1 = __ldg((const float4*)(res + (size_t)gr * HDIM + col + 4));
                v0.x += r0.x; v0.y += r0.y; v0.z += r0.z; v0.w += r0.w;
                v1.x += r1.x; v1.y += r1.y; v1.z += r1.z; v1.w += r1.w;
            }
            if (last) {
                if (r < n) {
                    *(float4*)(Y + (size_t)r * HDIM + col)     = v0;
                    *(float4*)(Y + (size_t)r * HDIM + col + 4) = v1;
                }
            } else {
                *(float4*)(xs + lr * 128 + col)     = v0;
                *(float4*)(xs + lr * 128 + col + 4) = v1;
            }
        }
        __syncthreads();
    }
}

// ---------------- launch ----------------
extern "C" void kernel_launch(void* const* d_in, const int* in_sizes, int n_in,
                              void* d_out, int out_size) {
    const float* z      = (const float*)d_in[0];
    const float* pos    = (const float*)d_in[1];
    const void*  ei     = d_in[2];
    const float* lin1_w = (const float*)d_in[3];
    const float* lin2_w = (const float*)d_in[4];
    const float* lin2_b = (const float*)d_in[5];
    const float* mlp0_w = (const float*)d_in[6];
    const float* mlp0_b = (const float*)d_in[7];
    const float* mlp2_w = (const float*)d_in[8];
    const float* mlp2_b = (const float*)d_in[9];
    const float* blk_w  = (const float*)d_in[10];
    const float* blk_b  = (const float*)d_in[11];
    const float* out1_w = (const float*)d_in[12];
    const float* out1_b = (const float*)d_in[13];
    const float* out2_w = (const float*)d_in[14];
    const float* out2_b = (const float*)d_in[15];
    float* out = (float*)d_out;

    const int n = in_sizes[0] / HDIM;
    const int E = in_sizes[2] / 2;

    float *x1p; __half *agghp;
    cudaGetSymbolAddress((void**)&x1p,   g_x1);
    cudaGetSymbolAddress((void**)&agghp, g_aggh);

    cudaFuncSetAttribute(fused_kernel, cudaFuncAttributeMaxDynamicSharedMemorySize, FUSED_SMEM);

    const int fblocks = (n + 255) / 256;
    const int n16 = n * 16;   // uint4 count of fp16 agg: 128 halfs = 16 uint4 per row

    detect_kernel<<<1, 256>>>((const unsigned*)ei, E);
    zero_kernel<<<(n16 + 255) / 256, 256>>>(n16);
    table_kernel<<<TPT, HDIM>>>(mlp0_w, mlp0_b, mlp2_w, mlp2_b);

    // x1 = z @ lin1^T
    Stages s1 = {};
    s1.W[0] = lin1_w; s1.bias[0] = nullptr; s1.res[0] = nullptr; s1.flags[0] = 0;
    s1.count = 1;
    fused_kernel<<<fblocks, 512, FUSED_SMEM>>>(z, x1p, s1, n, 0);

    // scatter: aggh[col] += fp16(x1[row] * lerp(tab, ew))
    edge_kernel<<<(E + 255) / 256, 256>>>(ei, pos, E);

    // fused tail (stage-1 input is fp16 agg)
    Stages s2 = {};
    s2.W[0] = lin2_w; s2.bias[0] = lin2_b; s2.res[0] = nullptr; s2.flags[0] = 1;
    s2.W[1] = blk_w;  s2.bias[1] = blk_b;  s2.res[1] = z;       s2.flags[1] = 0;
    s2.W[2] = out1_w; s2.bias[2] = out1_b; s2.res[2] = nullptr; s2.flags[2] = 1;
    s2.W[3] = out2_w; s2.bias[3] = out2_b; s2.res[3] = nullptr; s2.flags[3] = 0;
    s2.count = 4;
    fused_kernel<<<fblocks, 512, FUSED_SMEM>>>((const float*)agghp, out, s2, n, 1);
}